// round 17
// baseline (speedup 1.0000x reference)
#include <cuda_runtime.h>

#define T_STEPS 512
#define BATCH   4096
#define RING    128
#define RMASK   (RING - 1)
#define BLK     16
#define NBLK    (T_STEPS / BLK)   // 32
#define RBLK    (RING / BLK)      // 8

__device__ __align__(16) float g_h2[T_STEPS * 16];

typedef unsigned long long ull;

__device__ __forceinline__ ull ffma2(ull a, ull b, ull c) {
    ull d; asm("fma.rn.f32x2 %0, %1, %2, %3;" : "=l"(d) : "l"(a), "l"(b), "l"(c)); return d;
}
__device__ __forceinline__ ull fadd2(ull a, ull b) {
    ull d; asm("add.rn.f32x2 %0, %1, %2;" : "=l"(d) : "l"(a), "l"(b)); return d;
}
__device__ __forceinline__ float hsum2(ull a) {
    float lo, hi; asm("mov.b64 {%0, %1}, %2;" : "=f"(lo), "=f"(hi) : "l"(a)); return lo + hi;
}
__device__ __forceinline__ ull pack2(float lo, float hi) {
    ull d; asm("mov.b64 %0, {%1, %2};" : "=l"(d) : "f"(lo), "f"(hi)); return d;
}
__device__ __forceinline__ float tanhapx(float x) {
    float y; asm("tanh.approx.f32 %0, %1;" : "=f"(y) : "f"(x)); return y;
}
__device__ __forceinline__ unsigned ld_acq(const unsigned* p) {
    unsigned v;
    asm volatile("ld.acquire.cta.b32 %0, [%1];" : "=r"(v) : "l"(p) : "memory");
    return v;
}
__device__ __forceinline__ void st_rel(unsigned* p, unsigned v) {
    asm volatile("st.release.cta.b32 [%0], %1;" :: "l"(p), "r"(v) : "memory");
}
__device__ __forceinline__ void wait_ge(const unsigned* p, unsigned tgt) {
    if (ld_acq(p) >= tgt) return;
    while (ld_acq(p) < tgt) __nanosleep(64);
}

// R15 champion (59.9us) + ONE isolated change: w0/w1 LSTM bodies are now
// BRANCH-FREE (validated numerically in R10) and the per-iteration __syncwarp
// is removed. With zero divergence, the warp executes every STS/LDS as a
// single instruction in program order, so same-warp iter j's store is visible
// to iter j+1's load without any barrier. Gate pairs are exchanged with
// shfl_xor(16); both half-warps compute identical (c,h); stores are
// unconditional (benign same-value write collisions).
//
// 96 threads, 3 free-running warps:
//   warp0: layer0 step j   (self-recurrent; publishes h0 ring)
//   warp2: z[j] = (scl*Wih1)*h0[j] + scl*bias1  (h0 ring -> z ring)
//   warp1: layer1 step j   (z ring + own h1; writes g_h2)
// Per-16-step-block release/acquire counters; prescaled activations
// (sigmoid rows x0.5): vA = 0.5*tanh(aA)+0.5, vB = pmB*tanh(aB)+paB with
// g: pmB=1,paB=0 ; o: pmB=0.5,paB=0.5.
// Lane scheme: lane = u + 16*hi; gate A = hi ({i,f}), gate B = hi+2 ({g,o}).
__global__ void __launch_bounds__(96, 1) lstm_recur_kernel(
    const float* __restrict__ x,
    const float* __restrict__ Wih0, const float* __restrict__ Whh0,
    const float* __restrict__ bih0, const float* __restrict__ bhh0,
    const float* __restrict__ Wih1, const float* __restrict__ Whh1,
    const float* __restrict__ bih1, const float* __restrict__ bhh1)
{
    __shared__ float x_sh[T_STEPS];
    __shared__ __align__(16) float h0ring[RING][16];
    __shared__ __align__(16) float zring[RING][64];
    __shared__ __align__(16) float h1buf[2][16];
    __shared__ unsigned cnt[3];   // [0]=w0 blocks, [1]=w2, [2]=w1

    const int tid  = threadIdx.x;
    const int w    = tid >> 5;
    const int lane = tid & 31;
    const int u    = lane & 15;
    const int hi   = lane >> 4;

    // ---- init ----
#pragma unroll
    for (int r = 0; r < 6; r++) {
        const int idx = tid + 96 * r;
        if (idx < T_STEPS) x_sh[idx] = x[idx * BATCH + (BATCH - 1)];
    }
    if (tid < 16)  h0ring[RING - 1][tid] = 0.0f;   // h0[-1] = 0
    if (tid < 32)  ((float*)h1buf)[tid] = 0.0f;    // h1[-1] = 0
    if (tid < 3)   cnt[tid] = 0;

    // ---- per-lane weights, PRE-SCALED by the gate's activation scale ----
    const int giA = hi * 16 + u;          // i | f  -> sigmoid -> 0.5
    const int giB = (hi + 2) * 16 + u;    // g | o  -> tanh 1.0 | sigmoid 0.5
    const float sclA = 0.5f;
    const float sclB = hi ? 0.5f : 1.0f;
    const float pmB  = hi ? 0.5f : 1.0f;
    const float paB  = hi ? 0.5f : 0.0f;

    ull WA[8], WB[8];
    float biasA = 0.f, biasB = 0.f, wxA = 0.f, wxB = 0.f;
    if (w == 0) {
        const float2* Wp = (const float2*)Whh0;
#pragma unroll
        for (int k = 0; k < 8; k++) {
            const float2 a = Wp[giA * 8 + k], b = Wp[giB * 8 + k];
            WA[k] = pack2(a.x * sclA, a.y * sclA);
            WB[k] = pack2(b.x * sclB, b.y * sclB);
        }
        biasA = sclA * (bih0[giA] + bhh0[giA]);
        biasB = sclB * (bih0[giB] + bhh0[giB]);
        wxA   = sclA * Wih0[giA];
        wxB   = sclB * Wih0[giB];
    } else if (w == 2) {
        const float2* Wp = (const float2*)Wih1;
#pragma unroll
        for (int k = 0; k < 8; k++) {
            const float2 a = Wp[giA * 8 + k], b = Wp[giB * 8 + k];
            WA[k] = pack2(a.x * sclA, a.y * sclA);
            WB[k] = pack2(b.x * sclB, b.y * sclB);
        }
        biasA = sclA * (bih1[giA] + bhh1[giA]);
        biasB = sclB * (bih1[giB] + bhh1[giB]);
    } else {
        const float2* Wp = (const float2*)Whh1;
#pragma unroll
        for (int k = 0; k < 8; k++) {
            const float2 a = Wp[giA * 8 + k], b = Wp[giB * 8 + k];
            WA[k] = pack2(a.x * sclA, a.y * sclA);
            WB[k] = pack2(b.x * sclB, b.y * sclB);
        }
    }

    __syncthreads();   // the ONLY block-wide barrier

    if (w == 0) {
        // ================= layer0 (branch-free body) =================
        float h = 0.f, c = 0.f;
        for (int b = 0; b < NBLK; b++) {
            if (b >= RBLK) wait_ge(&cnt[1], b - RBLK + 1);
#pragma unroll 2
            for (int jj = 0; jj < BLK; jj++) {
                const int j = b * BLK + jj;
                const ulonglong2* hp = (const ulonglong2*)h0ring[(j + RING - 1) & RMASK];
                const ulonglong2 t0 = hp[0], t1 = hp[1], t2 = hp[2], t3 = hp[3];
                const ull op[8] = { t0.x, t0.y, t1.x, t1.y, t2.x, t2.y, t3.x, t3.y };
                const float xv = x_sh[j];

                ull a0 = ffma2(WA[0], op[0], pack2(fmaf(wxA, xv, biasA), 0.f));
                ull a1 = ffma2(WA[1], op[1], 0ull);
                ull b0 = ffma2(WB[0], op[0], pack2(fmaf(wxB, xv, biasB), 0.f));
                ull b1 = ffma2(WB[1], op[1], 0ull);
#pragma unroll
                for (int k = 2; k < 8; k += 2) {
                    a0 = ffma2(WA[k], op[k], a0);  a1 = ffma2(WA[k + 1], op[k + 1], a1);
                    b0 = ffma2(WB[k], op[k], b0);  b1 = ffma2(WB[k + 1], op[k + 1], b1);
                }
                const float vA = fmaf(0.5f, tanhapx(hsum2(fadd2(a0, a1))), 0.5f); // i|f
                const float vB = fmaf(pmB,  tanhapx(hsum2(fadd2(b0, b1))), paB);  // g|o
                const float pA = __shfl_xor_sync(0xffffffffu, vA, 16);
                const float pB = __shfl_xor_sync(0xffffffffu, vB, 16);
                // hi=0 owns (i,g), partner (f,o); hi=1 owns (f,o), partner (i,g)
                const float fg = hi ? vA : pA;
                const float ig = hi ? (pA * pB) : (vA * vB);
                const float og = hi ? vB : pB;
                c = fmaf(fg, c, ig);
                h = og * tanhapx(c);
                h0ring[j & RMASK][u] = h;     // all lanes, identical value
            }
            __syncwarp();
            if (lane == 0) st_rel(&cnt[0], b + 1);
        }
    } else if (w == 2) {
        // ================= z = (scaled Wih1)*h0 + scaled bias1 =================
        for (int b = 0; b < NBLK; b++) {
            wait_ge(&cnt[0], b + 1);
            if (b >= RBLK) wait_ge(&cnt[2], b - RBLK + 1);
            __syncwarp();
#pragma unroll 4
            for (int jj = 0; jj < BLK; jj++) {
                const int j = b * BLK + jj;
                const ulonglong2* hp = (const ulonglong2*)h0ring[j & RMASK];
                const ulonglong2 t0 = hp[0], t1 = hp[1], t2 = hp[2], t3 = hp[3];
                const ull op[8] = { t0.x, t0.y, t1.x, t1.y, t2.x, t2.y, t3.x, t3.y };

                ull a0 = ffma2(WA[0], op[0], pack2(biasA, 0.f));
                ull a1 = ffma2(WA[1], op[1], 0ull);
                ull b0 = ffma2(WB[0], op[0], pack2(biasB, 0.f));
                ull b1 = ffma2(WB[1], op[1], 0ull);
#pragma unroll
                for (int k = 2; k < 8; k += 2) {
                    a0 = ffma2(WA[k], op[k], a0);  a1 = ffma2(WA[k + 1], op[k + 1], a1);
                    b0 = ffma2(WB[k], op[k], b0);  b1 = ffma2(WB[k + 1], op[k + 1], b1);
                }
                zring[j & RMASK][giA] = hsum2(fadd2(a0, a1));
                zring[j & RMASK][giB] = hsum2(fadd2(b0, b1));
            }
            __syncwarp();
            if (lane == 0) st_rel(&cnt[1], b + 1);
        }
    } else {
        // ================= layer1 (branch-free body) =================
        float h = 0.f, c = 0.f;
        for (int b = 0; b < NBLK; b++) {
            wait_ge(&cnt[1], b + 1);
#pragma unroll 2
            for (int jj = 0; jj < BLK; jj++) {
                const int j = b * BLK + jj;
                const ulonglong2* hp = (const ulonglong2*)h1buf[j & 1];
                const ulonglong2 t0 = hp[0], t1 = hp[1], t2 = hp[2], t3 = hp[3];
                const ull op[8] = { t0.x, t0.y, t1.x, t1.y, t2.x, t2.y, t3.x, t3.y };
                const float zA = zring[j & RMASK][giA];
                const float zB = zring[j & RMASK][giB];

                ull a0 = ffma2(WA[0], op[0], pack2(zA, 0.f));
                ull a1 = ffma2(WA[1], op[1], 0ull);
                ull b0 = ffma2(WB[0], op[0], pack2(zB, 0.f));
                ull b1 = ffma2(WB[1], op[1], 0ull);
#pragma unroll
                for (int k = 2; k < 8; k += 2) {
                    a0 = ffma2(WA[k], op[k], a0);  a1 = ffma2(WA[k + 1], op[k + 1], a1);
                    b0 = ffma2(WB[k], op[k], b0);  b1 = ffma2(WB[k + 1], op[k + 1], b1);
                }
                const float vA = fmaf(0.5f, tanhapx(hsum2(fadd2(a0, a1))), 0.5f);
                const float vB = fmaf(pmB,  tanhapx(hsum2(fadd2(b0, b1))), paB);
                const float pA = __shfl_xor_sync(0xffffffffu, vA, 16);
                const float pB = __shfl_xor_sync(0xffffffffu, vB, 16);
                const float fg = hi ? vA : pA;
                const float ig = hi ? (pA * pB) : (vA * vB);
                const float og = hi ? vB : pB;
                c = fmaf(fg, c, ig);
                h = og * tanhapx(c);
                h1buf[(j + 1) & 1][u] = h;    // all lanes, identical value
                g_h2[j * 16 + u]     = h;     // all lanes, identical value
            }
            __syncwarp();
            if (lane == 0) st_rel(&cnt[2], b + 1);
        }
    }
}

// MLP 16 -> 64 (relu) -> 32 (relu) -> 1. One warp per timestep (512 blocks).
__global__ void __launch_bounds__(32) mlp_kernel(
    const float* __restrict__ W1, const float* __restrict__ b1,
    const float* __restrict__ W2, const float* __restrict__ b2,
    const float* __restrict__ W3, const float* __restrict__ b3,
    float* __restrict__ out)
{
    __shared__ __align__(16) float z1sh[64];
    const int t = blockIdx.x, lane = threadIdx.x;

    const float4* hp = (const float4*)(g_h2 + t * 16);
    const float4 h4[4] = { hp[0], hp[1], hp[2], hp[3] };

    float acc0 = b1[lane], acc1 = b1[lane + 32];
    const float4* w1a = (const float4*)(W1 + lane * 16);
    const float4* w1b = (const float4*)(W1 + (lane + 32) * 16);
#pragma unroll
    for (int q = 0; q < 4; q++) {
        const float4 wa = w1a[q], wb = w1b[q], hq = h4[q];
        acc0 = fmaf(wa.x, hq.x, acc0); acc0 = fmaf(wa.y, hq.y, acc0);
        acc0 = fmaf(wa.z, hq.z, acc0); acc0 = fmaf(wa.w, hq.w, acc0);
        acc1 = fmaf(wb.x, hq.x, acc1); acc1 = fmaf(wb.y, hq.y, acc1);
        acc1 = fmaf(wb.z, hq.z, acc1); acc1 = fmaf(wb.w, hq.w, acc1);
    }
    z1sh[lane]      = fmaxf(acc0, 0.0f);
    z1sh[lane + 32] = fmaxf(acc1, 0.0f);
    __syncwarp();

    float a2 = b2[lane];
    const float4* w2p = (const float4*)(W2 + lane * 64);
    const float4* z1p = (const float4*)z1sh;
#pragma unroll
    for (int q = 0; q < 16; q++) {
        const float4 wv = w2p[q], zv = z1p[q];
        a2 = fmaf(wv.x, zv.x, a2); a2 = fmaf(wv.y, zv.y, a2);
        a2 = fmaf(wv.z, zv.z, a2); a2 = fmaf(wv.w, zv.w, a2);
    }
    float v = fmaxf(a2, 0.0f) * W3[lane];
#pragma unroll
    for (int off = 16; off; off >>= 1)
        v += __shfl_xor_sync(0xffffffffu, v, off);
    if (lane == 0) out[t] = v + b3[0];
}

extern "C" void kernel_launch(void* const* d_in, const int* in_sizes, int n_in,
                              void* d_out, int out_size)
{
    const float* x    = (const float*)d_in[0];
    const float* Wih0 = (const float*)d_in[1];
    const float* Whh0 = (const float*)d_in[2];
    const float* bih0 = (const float*)d_in[3];
    const float* bhh0 = (const float*)d_in[4];
    const float* Wih1 = (const float*)d_in[5];
    const float* Whh1 = (const float*)d_in[6];
    const float* bih1 = (const float*)d_in[7];
    const float* bhh1 = (const float*)d_in[8];
    const float* W1   = (const float*)d_in[9];
    const float* b1   = (const float*)d_in[10];
    const float* W2   = (const float*)d_in[11];
    const float* b2   = (const float*)d_in[12];
    const float* W3   = (const float*)d_in[13];
    const float* b3   = (const float*)d_in[14];
    float* out = (float*)d_out;

    lstm_recur_kernel<<<1, 96>>>(x, Wih0, Whh0, bih0, bhh0,
                                 Wih1, Whh1, bih1, bhh1);
    mlp_kernel<<<T_STEPS, 32>>>(W1, b1, W2, b2, W3, b3, out);
}